// round 11
// baseline (speedup 1.0000x reference)
#include <cuda_runtime.h>
#include <cuda_fp16.h>
#include <cstdint>

#define NNODES 50000
#define DDIM   256
#define ETYPES 3
#define ET2    6
#define MEDGES 250000
#define NEDGES (ET2 * MEDGES)
#define KDIM   256
#define NSEG   (NNODES * ET2)            // 300000 (tgt,type) segments
#define MT     ((NNODES + 127) / 128)    // 391

// ---------------- R8 GEMM config (128x128, K=256) ----------------
#define GBM 128
#define GBN 128
#define GSTR 80
#define GBUF (128 * GSTR)
#define GNKT 8
#define OSTR 136

// ---------------- agg GEMM config (128x256, K=1536) ----------------
#define AG_ABUF (128 * 80)
#define AG_BBUF (256 * 80)
#define AG_SMA  0
#define AG_SMB  (2 * AG_ABUF)                 // 20480
#define AG_OSTR 264
#define AG_SMEM (128 * AG_OSTR * 2)           // 67584 (> 61440 mainloop use)
#define AG_K    1536
#define AG_NKT  48

// ---------------- scratch ----------------
__device__ __half g_aggh  [(size_t)NNODES * 1536];
__device__ __half g_msgsh [(size_t)NNODES * DDIM];
__device__ __half g_gih   [(size_t)NNODES * 768];
__device__ __half g_ghh   [(size_t)NNODES * 768];
__device__ float  g_h1    [(size_t)NNODES * DDIM];
__device__ __half g_hh    [(size_t)NNODES * DDIM];
__device__ float  g_inv   [NNODES];
__device__ float  g_bvec  [(size_t)NNODES * DDIM];
__device__ __half g_Wsth  [256 * 1536];        // permuted W: [c, i*256+d]
__device__ __half g_wihh  [768 * 256];
__device__ __half g_whhh  [768 * 256];
__device__ int    g_cnt2  [NSEG];
__device__ int    g_rp2   [NSEG + 1];
__device__ int    g_cur2  [NSEG];
__device__ int    g_eidx  [NEDGES];

// ---------------- setup kernels ----------------
__global__ void tohalf_kernel(const float* __restrict__ src, __half* __restrict__ dst, int n4) {
    int i = blockIdx.x * blockDim.x + threadIdx.x;
    if (i >= n4) return;
    float4 x = ((const float4*)src)[i];
    __half2* d = (__half2*)dst;
    d[2 * i]     = __floats2half2_rn(x.x, x.y);
    d[2 * i + 1] = __floats2half2_rn(x.z, x.w);
}

// Wst[c][i*256+d] = W[(i*256+c)][d], fp16
__global__ void wstack_kernel(const float* __restrict__ W, __half* __restrict__ dst) {
    int idx = blockIdx.x * blockDim.x + threadIdx.x;   // over 256*6*64
    if (idx >= 256 * 6 * 64) return;
    int c  = idx / (6 * 64);
    int r  = idx - c * (6 * 64);
    int i  = r >> 6, d4 = r & 63;
    float4 x = ((const float4*)(W + (size_t)(i * 256 + c) * 256))[d4];
    __half2* dp = (__half2*)(dst + (size_t)c * 1536 + i * 256 + d4 * 4);
    dp[0] = __floats2half2_rn(x.x, x.y);
    dp[1] = __floats2half2_rn(x.z, x.w);
}

__global__ void count2_kernel(const int* __restrict__ edges, int* __restrict__ cnt) {
    int g = blockIdx.x * blockDim.x + threadIdx.x;
    if (g >= NEDGES) return;
    int i = g / MEDGES;
    int e = g - i * MEDGES;
    int t;
    if (i < ETYPES) t = edges[((size_t)i * MEDGES + e) * 2 + 1];
    else            t = edges[((size_t)(i - ETYPES) * MEDGES + e) * 2 + 0];
    atomicAdd(&cnt[t * ET2 + i], 1);
}

// coarse single-block exclusive scan over NSEG ints
__global__ void scan2_kernel(const int* __restrict__ cnt, int* __restrict__ rowptr) {
    __shared__ int part[1024];
    const int CO = (NSEG + 1023) / 1024;   // 293
    int tid = threadIdx.x;
    int beg = tid * CO;
    int end = beg + CO; if (end > NSEG) end = NSEG;
    if (beg > NSEG) beg = NSEG;
    int s = 0;
    for (int k = beg; k < end; k++) s += cnt[k];
    part[tid] = s;
    __syncthreads();
    for (int off = 1; off < 1024; off <<= 1) {
        int v = (tid >= off) ? part[tid - off] : 0;
        __syncthreads();
        part[tid] += v;
        __syncthreads();
    }
    int pre = (tid == 0) ? 0 : part[tid - 1];
    for (int k = beg; k < end; k++) { rowptr[k] = pre; pre += cnt[k]; }
    if (tid == 1023) rowptr[NSEG] = pre;
}

__global__ void fill2_kernel(const int* __restrict__ edges, int* __restrict__ cursor,
                             int* __restrict__ eidx) {
    int g = blockIdx.x * blockDim.x + threadIdx.x;
    if (g >= NEDGES) return;
    int i = g / MEDGES;
    int e = g - i * MEDGES;
    int s, t;
    if (i < ETYPES) { int2 p = ((const int2*)edges)[(size_t)i * MEDGES + e]; s = p.x; t = p.y; }
    else            { int2 p = ((const int2*)edges)[(size_t)(i - ETYPES) * MEDGES + e]; s = p.y; t = p.x; }
    int pos = atomicAdd(&cursor[t * ET2 + i], 1);
    eidx[pos] = s;
}

__global__ void inv2_kernel(const int* __restrict__ rp2, float* __restrict__ inv) {
    int v = blockIdx.x * blockDim.x + threadIdx.x;
    if (v >= NNODES) return;
    int tot = rp2[v * ET2 + ET2] - rp2[v * ET2];
    float d = (tot == 0 ? 1.0f : (float)tot) + 1e-8f;
    inv[v] = 1.0f / d;
}

// bvec[v][c] = sum_i cnt_i[v] * b[i*256+c]
__global__ void bvec_kernel(const int* __restrict__ rp2, const float* __restrict__ b,
                            float* __restrict__ bvec) {
    int idx = blockIdx.x * blockDim.x + threadIdx.x;   // float4 over N*64
    if (idx >= NNODES * 64) return;
    int v = idx >> 6, c4 = idx & 63;
    float4 acc = make_float4(0.f, 0.f, 0.f, 0.f);
#pragma unroll
    for (int i = 0; i < ET2; i++) {
        float cnt = (float)(rp2[v * ET2 + i + 1] - rp2[v * ET2 + i]);
        float4 bb = ((const float4*)(b + i * 256))[c4];
        acc.x += cnt * bb.x; acc.y += cnt * bb.y;
        acc.z += cnt * bb.z; acc.w += cnt * bb.w;
    }
    ((float4*)bvec)[idx] = acc;
}

// ---------------- per-(node,type) aggregation of h ----------------
__global__ void agg_kernel(const __half* __restrict__ hh, const int* __restrict__ rp2,
                           const int* __restrict__ eidx, __half* __restrict__ aggh) {
    int w = (blockIdx.x * blockDim.x + threadIdx.x) >> 5;
    int lane = threadIdx.x & 31;
    if (w >= NNODES) return;
    int p[ET2 + 1];
#pragma unroll
    for (int i = 0; i <= ET2; i++) p[i] = rp2[w * ET2 + i];

#pragma unroll
    for (int i = 0; i < ET2; i++) {
        float a[8] = {0.f, 0.f, 0.f, 0.f, 0.f, 0.f, 0.f, 0.f};
        int e = p[i];
        for (; e + 1 < p[i + 1]; e += 2) {
            int s0 = eidx[e], s1 = eidx[e + 1];
            uint4 r0 = ((const uint4*)(hh + (size_t)s0 * 256))[lane];
            uint4 r1 = ((const uint4*)(hh + (size_t)s1 * 256))[lane];
            const __half2* h0 = (const __half2*)&r0;
            const __half2* h1 = (const __half2*)&r1;
#pragma unroll
            for (int q = 0; q < 4; q++) {
                float2 f0 = __half22float2(h0[q]);
                float2 f1 = __half22float2(h1[q]);
                a[2 * q]     += f0.x + f1.x;
                a[2 * q + 1] += f0.y + f1.y;
            }
        }
        if (e < p[i + 1]) {
            int s0 = eidx[e];
            uint4 r0 = ((const uint4*)(hh + (size_t)s0 * 256))[lane];
            const __half2* h0 = (const __half2*)&r0;
#pragma unroll
            for (int q = 0; q < 4; q++) {
                float2 f0 = __half22float2(h0[q]);
                a[2 * q]     += f0.x;
                a[2 * q + 1] += f0.y;
            }
        }
        union { uint4 u; __half2 h[4]; } o;
#pragma unroll
        for (int q = 0; q < 4; q++)
            o.h[q] = __floats2half2_rn(a[2 * q], a[2 * q + 1]);
        ((uint4*)(aggh + (size_t)w * 1536 + i * 256))[lane] = o.u;
    }
}

// ---------------- MMA helpers ----------------
__device__ __forceinline__ void mma_f16(float* c, const uint32_t* a, uint32_t b0, uint32_t b1) {
    asm volatile("mma.sync.aligned.m16n8k16.row.col.f32.f16.f16.f32 "
                 "{%0,%1,%2,%3}, {%4,%5,%6,%7}, {%8,%9}, {%0,%1,%2,%3};"
                 : "+f"(c[0]), "+f"(c[1]), "+f"(c[2]), "+f"(c[3])
                 : "r"(a[0]), "r"(a[1]), "r"(a[2]), "r"(a[3]), "r"(b0), "r"(b1));
}

#define LDSM_X4(r, addr)                                                        \
    asm volatile("ldmatrix.sync.aligned.m8n8.x4.shared.b16 {%0,%1,%2,%3}, [%4];" \
                 : "=r"((r)[0]), "=r"((r)[1]), "=r"((r)[2]), "=r"((r)[3])       \
                 : "r"(addr))

#define CP_ASYNC16(dst, src) \
    asm volatile("cp.async.cg.shared.global [%0], [%1], 16;" :: "r"(dst), "l"(src))

// ---------------- agg GEMM: msgs = (agg @ Wst^T + bvec) * inv, fp16 out ----------------
// A: [N,1536], B: [256,1536], C: [N,256]
__global__ __launch_bounds__(256, 1)
void hgemm_agg(const __half* __restrict__ A, const __half* __restrict__ B,
               const float* __restrict__ bvec, const float* __restrict__ inv,
               __half* __restrict__ C) {
    extern __shared__ __align__(16) char smem[];
    const uint32_t sbase = (uint32_t)__cvta_generic_to_shared(smem);

    const int tid  = threadIdx.x;
    const int lane = tid & 31;
    const int warp = tid >> 5;
    const int wm   = warp & 1;     // 2 m-slabs of 64
    const int wn   = warp >> 1;    // 4 n-slabs of 64
    const int blockRow = blockIdx.x * 128;

    const int l_row = tid >> 1;
    const int l_c2  = (tid & 1) * 2;

    auto issue = [&](int kt, int buf) {
        {
            int grow = blockRow + l_row; if (grow >= NNODES) grow = NNODES - 1;
            const __half* src = A + (size_t)grow * AG_K + kt * 32 + l_c2 * 8;
            uint32_t dst = sbase + AG_SMA + buf * AG_ABUF + l_row * 80 + l_c2 * 16;
            CP_ASYNC16(dst, src);
            CP_ASYNC16(dst + 16, src + 8);
        }
        {
            const __half* src = B + (size_t)tid * AG_K + kt * 32;
            uint32_t dst = sbase + AG_SMB + buf * AG_BBUF + tid * 80;
#pragma unroll
            for (int c = 0; c < 4; c++) CP_ASYNC16(dst + c * 16, src + c * 8);
        }
        asm volatile("cp.async.commit_group;");
    };

    float acc[4][8][4];
#pragma unroll
    for (int mt = 0; mt < 4; mt++)
#pragma unroll
        for (int nt = 0; nt < 8; nt++)
#pragma unroll
            for (int q = 0; q < 4; q++) acc[mt][nt][q] = 0.0f;

    issue(0, 0);
    issue(1, 1);

#pragma unroll 1
    for (int kt = 0; kt < AG_NKT; kt++) {
        if (kt + 1 < AG_NKT) asm volatile("cp.async.wait_group 1;");
        else                 asm volatile("cp.async.wait_group 0;");
        __syncthreads();

        const uint32_t as = sbase + AG_SMA + (kt & 1) * AG_ABUF;
        const uint32_t bs = sbase + AG_SMB + (kt & 1) * AG_BBUF;

#pragma unroll
        for (int ks = 0; ks < 2; ks++) {
            uint32_t af[4][4];
#pragma unroll
            for (int mt = 0; mt < 4; mt++) {
                int row = wm * 64 + mt * 16 + (lane & 15);
                LDSM_X4(af[mt], as + row * 80 + (ks * 2 + (lane >> 4)) * 16);
            }
            uint32_t bf[4][4];
#pragma unroll
            for (int bt = 0; bt < 4; bt++) {
                int nrow = wn * 64 + bt * 16 + (lane & 7) + ((lane >> 4) << 3);
                LDSM_X4(bf[bt], bs + nrow * 80 + (ks * 2 + ((lane >> 3) & 1)) * 16);
            }
#pragma unroll
            for (int mt = 0; mt < 4; mt++)
#pragma unroll
                for (int nt = 0; nt < 8; nt++)
                    mma_f16(acc[mt][nt], af[mt],
                            bf[nt >> 1][(nt & 1) * 2], bf[nt >> 1][(nt & 1) * 2 + 1]);
        }
        __syncthreads();
        if (kt + 2 < AG_NKT) issue(kt + 2, kt & 1);
    }

    // epilogue: (acc + bvec) * inv -> stage -> coalesced stores
    __half* stage = (__half*)smem;
#pragma unroll
    for (int mt = 0; mt < 4; mt++) {
        int rl = wm * 64 + mt * 16 + (lane >> 2);
        int r0 = blockRow + rl;
        int rc0 = r0 < NNODES ? r0 : NNODES - 1;
        int rc1 = r0 + 8 < NNODES ? r0 + 8 : NNODES - 1;
        float i0 = inv[rc0], i1 = inv[rc1];
#pragma unroll
        for (int nt = 0; nt < 8; nt++) {
            int cl = wn * 64 + nt * 8 + 2 * (lane & 3);
            float2 bv0 = *(const float2*)(bvec + (size_t)rc0 * 256 + cl);
            float2 bv1 = *(const float2*)(bvec + (size_t)rc1 * 256 + cl);
            *(__half2*)(stage + rl * AG_OSTR + cl) =
                __floats2half2_rn((acc[mt][nt][0] + bv0.x) * i0, (acc[mt][nt][1] + bv0.y) * i0);
            *(__half2*)(stage + (rl + 8) * AG_OSTR + cl) =
                __floats2half2_rn((acc[mt][nt][2] + bv1.x) * i1, (acc[mt][nt][3] + bv1.y) * i1);
        }
    }
    __syncthreads();

    const int r_ = tid >> 5, ch = tid & 31;
#pragma unroll
    for (int it = 0; it < 16; it++) {
        int row = r_ + it * 8;
        int grow = blockRow + row;
        uint4 v = *(const uint4*)(stage + row * AG_OSTR + ch * 8);
        if (grow < NNODES)
            *(uint4*)(C + (size_t)grow * 256 + ch * 8) = v;
    }
}

// ---------------- R8 GEMM (K=256): C(half) = A @ B^T + bias ----------------
__global__ __launch_bounds__(256, 2)
void hgemm_abT(const __half* __restrict__ A, const __half* __restrict__ B,
               const float* __restrict__ bias, __half* __restrict__ C,
               int Mrows, int Ncols) {
    __shared__ __align__(16) char smem[4 * GBUF];
    const uint32_t as_base = (uint32_t)__cvta_generic_to_shared(smem);
    const uint32_t bs_base = as_base + 2 * GBUF;

    const int tid  = threadIdx.x;
    const int lane = tid & 31;
    const int warp = tid >> 5;
    const int wm   = warp & 1;
    const int wn   = warp >> 1;

    const int blockRow = blockIdx.y * GBM;
    const int blockCol = blockIdx.x * GBN;

    const int l_row = tid >> 1;
    const int l_c2  = (tid & 1) * 2;

    float acc[4][4][4];
#pragma unroll
    for (int mt = 0; mt < 4; mt++)
#pragma unroll
        for (int nt = 0; nt < 4; nt++)
#pragma unroll
            for (int q = 0; q < 4; q++) acc[mt][nt][q] = 0.0f;

    auto issue = [&](int kt, int buf) {
        {
            int grow = blockRow + l_row; if (grow >= Mrows) grow = Mrows - 1;
            const __half* src = A + (size_t)grow * KDIM + kt * 32 + l_c2 * 8;
            uint32_t dst = as_base + buf * GBUF + l_row * GSTR + l_c2 * 16;
            CP_ASYNC16(dst, src);
            CP_ASYNC16(dst + 16, src + 8);
        }
        {
            const __half* src = B + (size_t)(blockCol + l_row) * KDIM + kt * 32 + l_c2 * 8;
            uint32_t dst = bs_base + buf * GBUF + l_row * GSTR + l_c2 * 16;
            CP_ASYNC16(dst, src);
            CP_ASYNC16(dst + 16, src + 8);
        }
        asm volatile("cp.async.commit_group;");
    };

    issue(0, 0);
    issue(1, 1);
    int buf = 0;

    for (int kt = 0; kt < GNKT; kt++) {
        if (kt + 1 < GNKT) asm volatile("cp.async.wait_group 1;");
        else               asm volatile("cp.async.wait_group 0;");
        __syncthreads();

        const uint32_t as = as_base + buf * GBUF;
        const uint32_t bs = bs_base + buf * GBUF;

#pragma unroll
        for (int ks = 0; ks < 2; ks++) {
            uint32_t af[4][4];
#pragma unroll
            for (int mt = 0; mt < 4; mt++) {
                int row = wm * 64 + mt * 16 + (lane & 15);
                LDSM_X4(af[mt], as + row * GSTR + (ks * 2 + (lane >> 4)) * 16);
            }
            uint32_t bf[2][4];
#pragma unroll
            for (int bt = 0; bt < 2; bt++) {
                int nrow = wn * 32 + bt * 16 + (lane & 7) + ((lane >> 4) << 3);
                LDSM_X4(bf[bt], bs + nrow * GSTR + (ks * 2 + ((lane >> 3) & 1)) * 16);
            }
#pragma unroll
            for (int mt = 0; mt < 4; mt++)
#pragma unroll
                for (int nt = 0; nt < 4; nt++)
                    mma_f16(acc[mt][nt], af[mt],
                            bf[nt >> 1][(nt & 1) * 2], bf[nt >> 1][(nt & 1) * 2 + 1]);
        }
        __syncthreads();
        buf ^= 1;
        if (kt + 2 < GNKT) issue(kt + 2, buf ^ 1);
    }

    __half* stage = (__half*)smem;
#pragma unroll
    for (int mt = 0; mt < 4; mt++) {
        int rl = wm * 64 + mt * 16 + (lane >> 2);
#pragma unroll
        for (int nt = 0; nt < 4; nt++) {
            int cl = wn * 32 + nt * 8 + 2 * (lane & 3);
            int cg = blockCol + cl;
            float bx = bias[cg], by = bias[cg + 1];
            *(__half2*)(stage + rl * OSTR + cl) =
                __floats2half2_rn(acc[mt][nt][0] + bx, acc[mt][nt][1] + by);
            *(__half2*)(stage + (rl + 8) * OSTR + cl) =
                __floats2half2_rn(acc[mt][nt][2] + bx, acc[mt][nt][3] + by);
        }
    }
    __syncthreads();

    const int r_ = tid >> 4, ch = tid & 15;
#pragma unroll
    for (int it = 0; it < 8; it++) {
        int row = r_ + it * 16;
        int grow = blockRow + row;
        uint4 v = *(const uint4*)(stage + row * OSTR + ch * 8);
        if (grow < Mrows)
            *(uint4*)(C + (size_t)grow * Ncols + blockCol + ch * 8) = v;
    }
}

// ---------------- GRU elementwise ----------------
__global__ void gru_kernel(const __half* __restrict__ gi, const __half* __restrict__ gh,
                           const float* __restrict__ h, float* __restrict__ out,
                           __half* __restrict__ hh) {
    int idx = blockIdx.x * blockDim.x + threadIdx.x;
    if (idx >= NNODES * (DDIM / 2)) return;
    int v = idx >> 7;
    int j = idx & 127;
    size_t b = (size_t)v * 384;
    const __half2* gi2 = (const __half2*)gi;
    const __half2* gh2 = (const __half2*)gh;
    float2 ir = __half22float2(gi2[b + j]);
    float2 hr = __half22float2(gh2[b + j]);
    float2 iz = __half22float2(gi2[b + 128 + j]);
    float2 hz = __half22float2(gh2[b + 128 + j]);
    float2 in_ = __half22float2(gi2[b + 256 + j]);
    float2 hn = __half22float2(gh2[b + 256 + j]);
    float2 hv = ((const float2*)h)[idx];

    float rx = 1.0f / (1.0f + expf(-(ir.x + hr.x)));
    float ry = 1.0f / (1.0f + expf(-(ir.y + hr.y)));
    float zx = 1.0f / (1.0f + expf(-(iz.x + hz.x)));
    float zy = 1.0f / (1.0f + expf(-(iz.y + hz.y)));
    float nx = tanhf(in_.x + rx * hn.x);
    float ny = tanhf(in_.y + ry * hn.y);
    float ox = (1.0f - zx) * nx + zx * hv.x;
    float oy = (1.0f - zy) * ny + zy * hv.y;
    ((float2*)out)[idx] = make_float2(ox, oy);
    if (hh != nullptr) ((__half2*)hh)[idx] = __floats2half2_rn(ox, oy);
}

// ---------------- launch ----------------
extern "C" void kernel_launch(void* const* d_in, const int* in_sizes, int n_in,
                              void* d_out, int out_size) {
    const float* node_states = (const float*)d_in[0];
    const float* W           = (const float*)d_in[1];
    const float* b           = (const float*)d_in[2];
    const float* w_ih        = (const float*)d_in[3];
    const float* w_hh        = (const float*)d_in[4];
    const float* b_ih        = (const float*)d_in[5];
    const float* b_hh        = (const float*)d_in[6];
    const int*   edges       = (const int*)d_in[7];
    float* out = (float*)d_out;

    float *h1, *inv, *bvec;
    __half *aggh, *msgsh, *gih, *ghh, *hh, *Wsth, *wihh, *whhh;
    int *cnt2, *rp2, *cur2, *eidx;
    cudaGetSymbolAddress((void**)&aggh,  g_aggh);
    cudaGetSymbolAddress((void**)&msgsh, g_msgsh);
    cudaGetSymbolAddress((void**)&gih,   g_gih);
    cudaGetSymbolAddress((void**)&ghh,   g_ghh);
    cudaGetSymbolAddress((void**)&h1,    g_h1);
    cudaGetSymbolAddress((void**)&hh,    g_hh);
    cudaGetSymbolAddress((void**)&inv,   g_inv);
    cudaGetSymbolAddress((void**)&bvec,  g_bvec);
    cudaGetSymbolAddress((void**)&Wsth,  g_Wsth);
    cudaGetSymbolAddress((void**)&wihh,  g_wihh);
    cudaGetSymbolAddress((void**)&whhh,  g_whhh);
    cudaGetSymbolAddress((void**)&cnt2,  g_cnt2);
    cudaGetSymbolAddress((void**)&rp2,   g_rp2);
    cudaGetSymbolAddress((void**)&cur2,  g_cur2);
    cudaGetSymbolAddress((void**)&eidx,  g_eidx);

    cudaFuncSetAttribute(hgemm_agg, cudaFuncAttributeMaxDynamicSharedMemorySize, AG_SMEM);

    // setup: operand conversion + CSR2 + divisor + bias vector
    wstack_kernel<<<(256 * 6 * 64 + 255) / 256, 256>>>(W, Wsth);
    tohalf_kernel<<<(768 * 256 / 4 + 255) / 256, 256>>>(w_ih, wihh, 768 * 256 / 4);
    tohalf_kernel<<<(768 * 256 / 4 + 255) / 256, 256>>>(w_hh, whhh, 768 * 256 / 4);
    tohalf_kernel<<<(NNODES * DDIM / 4 + 255) / 256, 256>>>(node_states, hh, NNODES * DDIM / 4);

    cudaMemsetAsync(cnt2, 0, NSEG * sizeof(int), 0);
    count2_kernel<<<(NEDGES + 255) / 256, 256>>>(edges, cnt2);
    scan2_kernel<<<1, 1024>>>(cnt2, rp2);
    cudaMemcpyAsync(cur2, rp2, NSEG * sizeof(int), cudaMemcpyDeviceToDevice, 0);
    fill2_kernel<<<(NEDGES + 255) / 256, 256>>>(edges, cur2, eidx);
    inv2_kernel<<<(NNODES + 255) / 256, 256>>>(rp2, inv);
    bvec_kernel<<<(NNODES * 64 + 255) / 256, 256>>>(rp2, b, bvec);

    const float* h = node_states;
    for (int t = 0; t < 2; t++) {
        agg_kernel<<<(NNODES * 32 + 255) / 256, 256>>>(hh, rp2, eidx, aggh);

        hgemm_agg<<<MT, 256, AG_SMEM>>>(aggh, Wsth, bvec, inv, msgsh);

        hgemm_abT<<<dim3(6, MT), 256>>>(msgsh, wihh, b_ih, gih, NNODES, 768);
        hgemm_abT<<<dim3(6, MT), 256>>>(hh, whhh, b_hh, ghh, NNODES, 768);

        float* hout = (t == 0) ? h1 : out;
        gru_kernel<<<(NNODES * DDIM / 2 + 255) / 256, 256>>>(gih, ghh, h, hout,
                                                             (t == 0) ? hh : nullptr);
        h = hout;
    }
}

// round 12
// speedup vs baseline: 1.2524x; 1.2524x over previous
#include <cuda_runtime.h>
#include <cuda_fp16.h>
#include <cstdint>

#define NNODES 50000
#define DDIM   256
#define ETYPES 3
#define ET2    6
#define MEDGES 250000
#define NEDGES (ET2 * MEDGES)
#define KDIM   256

// ---------------- fp16 HMMA GEMM config ----------------
#define GBM 128
#define GBN 128
#define GSTR 80
#define GBUF (128 * GSTR)     // 10240 B per chunk buffer
#define GNKT 8
#define OSTR 136
#define GSMEM (8 * GBUF)      // 4 A + 4 B buffers = 81920 B (dynamic)

// ---------------- scratch (no cudaMalloc allowed) ----------------
__device__ __half g_proph [(size_t)NNODES * 1536];
__device__ __half g_msgsh [(size_t)NNODES * DDIM];
__device__ __half g_gih   [(size_t)NNODES * 768];
__device__ __half g_ghh   [(size_t)NNODES * 768];
__device__ float  g_h1    [(size_t)NNODES * DDIM];
__device__ __half g_hh    [(size_t)NNODES * DDIM];
__device__ __half g_Wh    [1536 * 256];
__device__ __half g_wihh  [768 * 256];
__device__ __half g_whhh  [768 * 256];
__device__ int    g_cnt   [NNODES];
__device__ int    g_rowptr[NNODES + 1];
__device__ int    g_cursor[NNODES];
__device__ int    g_eidx  [NEDGES];

// ---------------- small kernels ----------------
__global__ void tohalf_kernel(const float* __restrict__ src, __half* __restrict__ dst, int n4) {
    int i = blockIdx.x * blockDim.x + threadIdx.x;
    if (i >= n4) return;
    float4 x = ((const float4*)src)[i];
    __half2* d = (__half2*)dst;
    d[2 * i]     = __floats2half2_rn(x.x, x.y);
    d[2 * i + 1] = __floats2half2_rn(x.z, x.w);
}

__global__ void count_kernel(const int* __restrict__ edges, int* __restrict__ cnt) {
    int g = blockIdx.x * blockDim.x + threadIdx.x;
    if (g >= NEDGES) return;
    int i = g / MEDGES;
    int e = g - i * MEDGES;
    int t;
    if (i < ETYPES) t = edges[((size_t)i * MEDGES + e) * 2 + 1];
    else            t = edges[((size_t)(i - ETYPES) * MEDGES + e) * 2 + 0];
    atomicAdd(&cnt[t], 1);
}

// single-block exclusive scan over 50000 ints
__global__ void scan_kernel(const int* __restrict__ cnt, int* __restrict__ rowptr) {
    __shared__ int s[1024];
    __shared__ int carry;
    int tid = threadIdx.x;
    if (tid == 0) carry = 0;
    __syncthreads();
    for (int base = 0; base < NNODES; base += 1024) {
        int x = (base + tid < NNODES) ? cnt[base + tid] : 0;
        s[tid] = x;
        __syncthreads();
        for (int off = 1; off < 1024; off <<= 1) {
            int t = (tid >= off) ? s[tid - off] : 0;
            __syncthreads();
            s[tid] += t;
            __syncthreads();
        }
        if (base + tid < NNODES) rowptr[base + tid] = carry + s[tid] - x;
        __syncthreads();
        if (tid == 0) carry += s[1023];
        __syncthreads();
    }
    if (tid == 0) rowptr[NNODES] = carry;
}

// fill CSR adjacency: eidx[pos] = src*6 + type  (prop row id)
__global__ void fill_kernel(const int* __restrict__ edges, int* __restrict__ cursor,
                            int* __restrict__ eidx) {
    int g = blockIdx.x * blockDim.x + threadIdx.x;
    if (g >= NEDGES) return;
    int i = g / MEDGES;
    int e = g - i * MEDGES;
    int s, t;
    if (i < ETYPES) { int2 p = ((const int2*)edges)[(size_t)i * MEDGES + e]; s = p.x; t = p.y; }
    else            { int2 p = ((const int2*)edges)[(size_t)(i - ETYPES) * MEDGES + e]; s = p.y; t = p.x; }
    int pos = atomicAdd(&cursor[t], 1);
    eidx[pos] = s * 6 + i;
}

// ---------------- atomic-free aggregation (4-edge unroll) ----------------
__global__ void aggregate_kernel(const __half* __restrict__ proph,
                                 const int* __restrict__ rowptr,
                                 const int* __restrict__ eidx,
                                 __half* __restrict__ msgsh) {
    int w = (blockIdx.x * blockDim.x + threadIdx.x) >> 5;
    int lane = threadIdx.x & 31;
    if (w >= NNODES) return;
    int beg = rowptr[w], end = rowptr[w + 1];

    float a[8] = {0.f, 0.f, 0.f, 0.f, 0.f, 0.f, 0.f, 0.f};
    int e = beg;
    for (; e + 3 < end; e += 4) {
        int r0 = eidx[e], r1 = eidx[e + 1], r2 = eidx[e + 2], r3 = eidx[e + 3];
        uint4 q0 = __ldcs((const uint4*)(proph + (size_t)r0 * 256) + lane);
        uint4 q1 = __ldcs((const uint4*)(proph + (size_t)r1 * 256) + lane);
        uint4 q2 = __ldcs((const uint4*)(proph + (size_t)r2 * 256) + lane);
        uint4 q3 = __ldcs((const uint4*)(proph + (size_t)r3 * 256) + lane);
        const __half2* h0 = (const __half2*)&q0;
        const __half2* h1 = (const __half2*)&q1;
        const __half2* h2 = (const __half2*)&q2;
        const __half2* h3 = (const __half2*)&q3;
#pragma unroll
        for (int q = 0; q < 4; q++) {
            float2 f0 = __half22float2(h0[q]);
            float2 f1 = __half22float2(h1[q]);
            float2 f2 = __half22float2(h2[q]);
            float2 f3 = __half22float2(h3[q]);
            a[2 * q]     += (f0.x + f1.x) + (f2.x + f3.x);
            a[2 * q + 1] += (f0.y + f1.y) + (f2.y + f3.y);
        }
    }
    for (; e < end; e++) {
        int r0 = eidx[e];
        uint4 q0 = __ldcs((const uint4*)(proph + (size_t)r0 * 256) + lane);
        const __half2* h0 = (const __half2*)&q0;
#pragma unroll
        for (int q = 0; q < 4; q++) {
            float2 f0 = __half22float2(h0[q]);
            a[2 * q]     += f0.x;
            a[2 * q + 1] += f0.y;
        }
    }

    int c = end - beg;
    float d = (c == 0 ? 1.0f : (float)c) + 1e-8f;
    float sc = 1.0f / d;
    union { uint4 u; __half2 h[4]; } o;
#pragma unroll
    for (int q = 0; q < 4; q++)
        o.h[q] = __floats2half2_rn(a[2 * q] * sc, a[2 * q + 1] * sc);
    ((uint4*)(msgsh + (size_t)w * 256))[lane] = o.u;
}

// ---------------- fp16 tensor-core GEMM: C(half) = A @ B^T + bias ----------------
__device__ __forceinline__ void mma_f16(float* c, const uint32_t* a, uint32_t b0, uint32_t b1) {
    asm volatile("mma.sync.aligned.m16n8k16.row.col.f32.f16.f16.f32 "
                 "{%0,%1,%2,%3}, {%4,%5,%6,%7}, {%8,%9}, {%0,%1,%2,%3};"
                 : "+f"(c[0]), "+f"(c[1]), "+f"(c[2]), "+f"(c[3])
                 : "r"(a[0]), "r"(a[1]), "r"(a[2]), "r"(a[3]), "r"(b0), "r"(b1));
}

#define LDSM_X4(r, addr)                                                        \
    asm volatile("ldmatrix.sync.aligned.m8n8.x4.shared.b16 {%0,%1,%2,%3}, [%4];" \
                 : "=r"((r)[0]), "=r"((r)[1]), "=r"((r)[2]), "=r"((r)[3])       \
                 : "r"(addr))

#define CP_ASYNC16(dst, src) \
    asm volatile("cp.async.cg.shared.global [%0], [%1], 16;" :: "r"(dst), "l"(src))

// 4-stage cp.async ring, single __syncthreads per k-tile
__global__ __launch_bounds__(256, 2)
void hgemm_abT(const __half* __restrict__ A, const __half* __restrict__ B,
               const float* __restrict__ bias, __half* __restrict__ C,
               int Mrows, int Ncols) {
    extern __shared__ __align__(16) char smem[];   // 8 * GBUF dynamic
    const uint32_t as_base = (uint32_t)__cvta_generic_to_shared(smem);
    const uint32_t bs_base = as_base + 4 * GBUF;

    const int tid  = threadIdx.x;
    const int lane = tid & 31;
    const int warp = tid >> 5;
    const int wm   = warp & 1;
    const int wn   = warp >> 1;

    const int blockRow = blockIdx.y * GBM;
    const int blockCol = blockIdx.x * GBN;

    const int l_row = tid >> 1;
    const int l_c2  = (tid & 1) * 2;

    float acc[4][4][4];
#pragma unroll
    for (int mt = 0; mt < 4; mt++)
#pragma unroll
        for (int nt = 0; nt < 4; nt++)
#pragma unroll
            for (int q = 0; q < 4; q++) acc[mt][nt][q] = 0.0f;

    auto issue = [&](int kt) {
        const int buf = kt & 3;
        {
            int grow = blockRow + l_row; if (grow >= Mrows) grow = Mrows - 1;
            const __half* src = A + (size_t)grow * KDIM + kt * 32 + l_c2 * 8;
            uint32_t dst = as_base + buf * GBUF + l_row * GSTR + l_c2 * 16;
            CP_ASYNC16(dst, src);
            CP_ASYNC16(dst + 16, src + 8);
        }
        {
            const __half* src = B + (size_t)(blockCol + l_row) * KDIM + kt * 32 + l_c2 * 8;
            uint32_t dst = bs_base + buf * GBUF + l_row * GSTR + l_c2 * 16;
            CP_ASYNC16(dst, src);
            CP_ASYNC16(dst + 16, src + 8);
        }
        asm volatile("cp.async.commit_group;");
    };

    issue(0);
    issue(1);
    issue(2);

#pragma unroll 1
    for (int kt = 0; kt < GNKT; kt++) {
        if (kt < GNKT - 2)      asm volatile("cp.async.wait_group 2;");
        else if (kt == GNKT - 2) asm volatile("cp.async.wait_group 1;");
        else                     asm volatile("cp.async.wait_group 0;");
        __syncthreads();

        const uint32_t as = as_base + (kt & 3) * GBUF;
        const uint32_t bs = bs_base + (kt & 3) * GBUF;

#pragma unroll
        for (int ks = 0; ks < 2; ks++) {
            uint32_t af[4][4];
#pragma unroll
            for (int mt = 0; mt < 4; mt++) {
                int row = wm * 64 + mt * 16 + (lane & 15);
                LDSM_X4(af[mt], as + row * GSTR + (ks * 2 + (lane >> 4)) * 16);
            }
            uint32_t bf[2][4];
#pragma unroll
            for (int bt = 0; bt < 2; bt++) {
                int nrow = wn * 32 + bt * 16 + (lane & 7) + ((lane >> 4) << 3);
                LDSM_X4(bf[bt], bs + nrow * GSTR + (ks * 2 + ((lane >> 3) & 1)) * 16);
            }
#pragma unroll
            for (int mt = 0; mt < 4; mt++)
#pragma unroll
                for (int nt = 0; nt < 4; nt++)
                    mma_f16(acc[mt][nt], af[mt],
                            bf[nt >> 1][(nt & 1) * 2], bf[nt >> 1][(nt & 1) * 2 + 1]);
        }
        if (kt + 3 < GNKT) issue(kt + 3);
    }

    // all warps must finish MMA before smem is reused as the output stage
    __syncthreads();

    __half* stage = (__half*)smem;
#pragma unroll
    for (int mt = 0; mt < 4; mt++) {
        int rl = wm * 64 + mt * 16 + (lane >> 2);
#pragma unroll
        for (int nt = 0; nt < 4; nt++) {
            int cl = wn * 32 + nt * 8 + 2 * (lane & 3);
            int cg = blockCol + cl;
            float bx = bias[cg], by = bias[cg + 1];
            *(__half2*)(stage + rl * OSTR + cl) =
                __floats2half2_rn(acc[mt][nt][0] + bx, acc[mt][nt][1] + by);
            *(__half2*)(stage + (rl + 8) * OSTR + cl) =
                __floats2half2_rn(acc[mt][nt][2] + bx, acc[mt][nt][3] + by);
        }
    }
    __syncthreads();

    const int r_ = tid >> 4, ch = tid & 15;
#pragma unroll
    for (int it = 0; it < 8; it++) {
        int row = r_ + it * 16;
        int grow = blockRow + row;
        uint4 v = *(const uint4*)(stage + row * OSTR + ch * 8);
        if (grow < Mrows)
            *(uint4*)(C + (size_t)grow * Ncols + blockCol + ch * 8) = v;
    }
}

// ---------------- GRU elementwise (half2 gates) ----------------
__global__ void gru_kernel(const __half* __restrict__ gi, const __half* __restrict__ gh,
                           const float* __restrict__ h, float* __restrict__ out,
                           __half* __restrict__ hh) {
    int idx = blockIdx.x * blockDim.x + threadIdx.x;
    if (idx >= NNODES * (DDIM / 2)) return;
    int v = idx >> 7;
    int j = idx & 127;
    size_t b = (size_t)v * 384;
    const __half2* gi2 = (const __half2*)gi;
    const __half2* gh2 = (const __half2*)gh;
    float2 ir = __half22float2(gi2[b + j]);
    float2 hr = __half22float2(gh2[b + j]);
    float2 iz = __half22float2(gi2[b + 128 + j]);
    float2 hz = __half22float2(gh2[b + 128 + j]);
    float2 in_ = __half22float2(gi2[b + 256 + j]);
    float2 hn = __half22float2(gh2[b + 256 + j]);
    float2 hv = ((const float2*)h)[idx];

    float rx = 1.0f / (1.0f + expf(-(ir.x + hr.x)));
    float ry = 1.0f / (1.0f + expf(-(ir.y + hr.y)));
    float zx = 1.0f / (1.0f + expf(-(iz.x + hz.x)));
    float zy = 1.0f / (1.0f + expf(-(iz.y + hz.y)));
    float nx = tanhf(in_.x + rx * hn.x);
    float ny = tanhf(in_.y + ry * hn.y);
    float ox = (1.0f - zx) * nx + zx * hv.x;
    float oy = (1.0f - zy) * ny + zy * hv.y;
    ((float2*)out)[idx] = make_float2(ox, oy);
    if (hh != nullptr) ((__half2*)hh)[idx] = __floats2half2_rn(ox, oy);
}

// ---------------- launch ----------------
extern "C" void kernel_launch(void* const* d_in, const int* in_sizes, int n_in,
                              void* d_out, int out_size) {
    const float* node_states = (const float*)d_in[0];
    const float* W           = (const float*)d_in[1];
    const float* b           = (const float*)d_in[2];
    const float* w_ih        = (const float*)d_in[3];
    const float* w_hh        = (const float*)d_in[4];
    const float* b_ih        = (const float*)d_in[5];
    const float* b_hh        = (const float*)d_in[6];
    const int*   edges       = (const int*)d_in[7];
    float* out = (float*)d_out;

    float *h1;
    __half *proph, *msgsh, *gih, *ghh, *hh, *Wh, *wihh, *whhh;
    int *cnt, *rowptr, *cursor, *eidx;
    cudaGetSymbolAddress((void**)&proph,  g_proph);
    cudaGetSymbolAddress((void**)&msgsh,  g_msgsh);
    cudaGetSymbolAddress((void**)&gih,    g_gih);
    cudaGetSymbolAddress((void**)&ghh,    g_ghh);
    cudaGetSymbolAddress((void**)&h1,     g_h1);
    cudaGetSymbolAddress((void**)&hh,     g_hh);
    cudaGetSymbolAddress((void**)&Wh,     g_Wh);
    cudaGetSymbolAddress((void**)&wihh,   g_wihh);
    cudaGetSymbolAddress((void**)&whhh,   g_whhh);
    cudaGetSymbolAddress((void**)&cnt,    g_cnt);
    cudaGetSymbolAddress((void**)&rowptr, g_rowptr);
    cudaGetSymbolAddress((void**)&cursor, g_cursor);
    cudaGetSymbolAddress((void**)&eidx,   g_eidx);

    cudaFuncSetAttribute(hgemm_abT, cudaFuncAttributeMaxDynamicSharedMemorySize, GSMEM);

    // operand conversion
    tohalf_kernel<<<(1536 * 256 / 4 + 255) / 256, 256>>>(W, Wh, 1536 * 256 / 4);
    tohalf_kernel<<<(768 * 256 / 4 + 255) / 256, 256>>>(w_ih, wihh, 768 * 256 / 4);
    tohalf_kernel<<<(768 * 256 / 4 + 255) / 256, 256>>>(w_hh, whhh, 768 * 256 / 4);
    tohalf_kernel<<<(NNODES * DDIM / 4 + 255) / 256, 256>>>(node_states, hh, NNODES * DDIM / 4);

    // CSR build (once per launch)
    cudaMemsetAsync(cnt, 0, NNODES * sizeof(int), 0);
    count_kernel<<<(NEDGES + 255) / 256, 256>>>(edges, cnt);
    scan_kernel<<<1, 1024>>>(cnt, rowptr);
    cudaMemcpyAsync(cursor, rowptr, NNODES * sizeof(int), cudaMemcpyDeviceToDevice, 0);
    fill_kernel<<<(NEDGES + 255) / 256, 256>>>(edges, cursor, eidx);

    const int MT = (NNODES + GBM - 1) / GBM;
    const float* h = node_states;
    for (int t = 0; t < 2; t++) {
        hgemm_abT<<<dim3(1536 / GBN, MT), 256, GSMEM>>>(hh, Wh, b, proph, NNODES, 1536);

        aggregate_kernel<<<(NNODES * 32 + 255) / 256, 256>>>(proph, rowptr, eidx, msgsh);

        hgemm_abT<<<dim3(768 / GBN, MT), 256, GSMEM>>>(msgsh, wihh, b_ih, gih, NNODES, 768);
        hgemm_abT<<<dim3(768 / GBN, MT), 256, GSMEM>>>(hh, whhh, b_hh, ghh, NNODES, 768);

        float* hout = (t == 0) ? h1 : out;
        gru_kernel<<<(NNODES * DDIM / 2 + 255) / 256, 256>>>(gih, ghh, h, hout,
                                                             (t == 0) ? hh : nullptr);
        h = hout;
    }
}

// round 13
// speedup vs baseline: 1.3606x; 1.0863x over previous
#include <cuda_runtime.h>
#include <cuda_fp16.h>
#include <cstdint>

#define NNODES 50000
#define DDIM   256
#define ETYPES 3
#define ET2    6
#define MEDGES 250000
#define NEDGES (ET2 * MEDGES)
#define KDIM   256

// ---------------- fp16 HMMA GEMM config (R8, proven) ----------------
#define GBM 128
#define GBN 128
#define GSTR 80
#define GBUF (128 * GSTR)
#define GNKT 8
#define OSTR 136

// ---------------- scratch (no cudaMalloc allowed) ----------------
__device__ __half g_proph [(size_t)NNODES * 1536];
__device__ __half g_msgsh [(size_t)NNODES * DDIM];
__device__ __half g_gih   [(size_t)NNODES * 768];
__device__ __half g_ghh   [(size_t)NNODES * 768];
__device__ float  g_h1    [(size_t)NNODES * DDIM];
__device__ __half g_hh    [(size_t)NNODES * DDIM];
__device__ __half g_Wh    [1536 * 256];
__device__ __half g_wihh  [768 * 256];
__device__ __half g_whhh  [768 * 256];
__device__ int    g_cnt   [NNODES];
__device__ int    g_rowptr[NNODES + 1];
__device__ int    g_cursor[NNODES];
__device__ int    g_eidx  [NEDGES];

// ---------------- small kernels ----------------
__global__ void tohalf_kernel(const float* __restrict__ src, __half* __restrict__ dst, int n4) {
    int i = blockIdx.x * blockDim.x + threadIdx.x;
    if (i >= n4) return;
    float4 x = ((const float4*)src)[i];
    __half2* d = (__half2*)dst;
    d[2 * i]     = __floats2half2_rn(x.x, x.y);
    d[2 * i + 1] = __floats2half2_rn(x.z, x.w);
}

__global__ void count_kernel(const int* __restrict__ edges, int* __restrict__ cnt) {
    int g = blockIdx.x * blockDim.x + threadIdx.x;
    if (g >= NEDGES) return;
    int i = g / MEDGES;
    int e = g - i * MEDGES;
    int t;
    if (i < ETYPES) t = edges[((size_t)i * MEDGES + e) * 2 + 1];
    else            t = edges[((size_t)(i - ETYPES) * MEDGES + e) * 2 + 0];
    atomicAdd(&cnt[t], 1);
}

__global__ void scan_kernel(const int* __restrict__ cnt, int* __restrict__ rowptr) {
    __shared__ int s[1024];
    __shared__ int carry;
    int tid = threadIdx.x;
    if (tid == 0) carry = 0;
    __syncthreads();
    for (int base = 0; base < NNODES; base += 1024) {
        int x = (base + tid < NNODES) ? cnt[base + tid] : 0;
        s[tid] = x;
        __syncthreads();
        for (int off = 1; off < 1024; off <<= 1) {
            int t = (tid >= off) ? s[tid - off] : 0;
            __syncthreads();
            s[tid] += t;
            __syncthreads();
        }
        if (base + tid < NNODES) rowptr[base + tid] = carry + s[tid] - x;
        __syncthreads();
        if (tid == 0) carry += s[1023];
        __syncthreads();
    }
    if (tid == 0) rowptr[NNODES] = carry;
}

__global__ void fill_kernel(const int* __restrict__ edges, int* __restrict__ cursor,
                            int* __restrict__ eidx) {
    int g = blockIdx.x * blockDim.x + threadIdx.x;
    if (g >= NEDGES) return;
    int i = g / MEDGES;
    int e = g - i * MEDGES;
    int s, t;
    if (i < ETYPES) { int2 p = ((const int2*)edges)[(size_t)i * MEDGES + e]; s = p.x; t = p.y; }
    else            { int2 p = ((const int2*)edges)[(size_t)(i - ETYPES) * MEDGES + e]; s = p.y; t = p.x; }
    int pos = atomicAdd(&cursor[t], 1);
    eidx[pos] = s * 6 + i;
}

// ---------------- atomic-free aggregation ----------------
__global__ void aggregate_kernel(const __half* __restrict__ proph,
                                 const int* __restrict__ rowptr,
                                 const int* __restrict__ eidx,
                                 __half* __restrict__ msgsh) {
    int w = (blockIdx.x * blockDim.x + threadIdx.x) >> 5;
    int lane = threadIdx.x & 31;
    if (w >= NNODES) return;
    int beg = rowptr[w], end = rowptr[w + 1];

    float a[8] = {0.f, 0.f, 0.f, 0.f, 0.f, 0.f, 0.f, 0.f};
    int e = beg;
    for (; e + 1 < end; e += 2) {
        int r0 = eidx[e], r1 = eidx[e + 1];
        uint4 raw0 = __ldcs((const uint4*)(proph + (size_t)r0 * 256) + lane);
        uint4 raw1 = __ldcs((const uint4*)(proph + (size_t)r1 * 256) + lane);
        const __half2* h0 = (const __half2*)&raw0;
        const __half2* h1 = (const __half2*)&raw1;
#pragma unroll
        for (int q = 0; q < 4; q++) {
            float2 f0 = __half22float2(h0[q]);
            float2 f1 = __half22float2(h1[q]);
            a[2 * q]     += f0.x + f1.x;
            a[2 * q + 1] += f0.y + f1.y;
        }
    }
    if (e < end) {
        int r0 = eidx[e];
        uint4 raw0 = __ldcs((const uint4*)(proph + (size_t)r0 * 256) + lane);
        const __half2* h0 = (const __half2*)&raw0;
#pragma unroll
        for (int q = 0; q < 4; q++) {
            float2 f0 = __half22float2(h0[q]);
            a[2 * q]     += f0.x;
            a[2 * q + 1] += f0.y;
        }
    }

    int c = end - beg;
    float d = (c == 0 ? 1.0f : (float)c) + 1e-8f;
    float sc = 1.0f / d;
    union { uint4 u; __half2 h[4]; } o;
#pragma unroll
    for (int q = 0; q < 4; q++)
        o.h[q] = __floats2half2_rn(a[2 * q] * sc, a[2 * q + 1] * sc);
    ((uint4*)(msgsh + (size_t)w * 256))[lane] = o.u;
}

// ---------------- fp16 tensor-core GEMM (R8): C(half) = A @ B^T + bias ----------------
__device__ __forceinline__ void mma_f16(float* c, const uint32_t* a, uint32_t b0, uint32_t b1) {
    asm volatile("mma.sync.aligned.m16n8k16.row.col.f32.f16.f16.f32 "
                 "{%0,%1,%2,%3}, {%4,%5,%6,%7}, {%8,%9}, {%0,%1,%2,%3};"
                 : "+f"(c[0]), "+f"(c[1]), "+f"(c[2]), "+f"(c[3])
                 : "r"(a[0]), "r"(a[1]), "r"(a[2]), "r"(a[3]), "r"(b0), "r"(b1));
}

#define LDSM_X4(r, addr)                                                        \
    asm volatile("ldmatrix.sync.aligned.m8n8.x4.shared.b16 {%0,%1,%2,%3}, [%4];" \
                 : "=r"((r)[0]), "=r"((r)[1]), "=r"((r)[2]), "=r"((r)[3])       \
                 : "r"(addr))

#define CP_ASYNC16(dst, src) \
    asm volatile("cp.async.cg.shared.global [%0], [%1], 16;" :: "r"(dst), "l"(src))

__global__ __launch_bounds__(256, 2)
void hgemm_abT(const __half* __restrict__ A, const __half* __restrict__ B,
               const float* __restrict__ bias, __half* __restrict__ C,
               int Mrows, int Ncols) {
    __shared__ __align__(16) char smem[4 * GBUF];
    const uint32_t as_base = (uint32_t)__cvta_generic_to_shared(smem);
    const uint32_t bs_base = as_base + 2 * GBUF;

    const int tid  = threadIdx.x;
    const int lane = tid & 31;
    const int warp = tid >> 5;
    const int wm   = warp & 1;
    const int wn   = warp >> 1;

    const int blockRow = blockIdx.y * GBM;
    const int blockCol = blockIdx.x * GBN;

    const int l_row = tid >> 1;
    const int l_c2  = (tid & 1) * 2;

    float acc[4][4][4];
#pragma unroll
    for (int mt = 0; mt < 4; mt++)
#pragma unroll
        for (int nt = 0; nt < 4; nt++)
#pragma unroll
            for (int q = 0; q < 4; q++) acc[mt][nt][q] = 0.0f;

    auto issue = [&](int kt, int buf) {
        {
            int grow = blockRow + l_row; if (grow >= Mrows) grow = Mrows - 1;
            const __half* src = A + (size_t)grow * KDIM + kt * 32 + l_c2 * 8;
            uint32_t dst = as_base + buf * GBUF + l_row * GSTR + l_c2 * 16;
            CP_ASYNC16(dst, src);
            CP_ASYNC16(dst + 16, src + 8);
        }
        {
            const __half* src = B + (size_t)(blockCol + l_row) * KDIM + kt * 32 + l_c2 * 8;
            uint32_t dst = bs_base + buf * GBUF + l_row * GSTR + l_c2 * 16;
            CP_ASYNC16(dst, src);
            CP_ASYNC16(dst + 16, src + 8);
        }
        asm volatile("cp.async.commit_group;");
    };

    issue(0, 0);
    issue(1, 1);
    int buf = 0;

    for (int kt = 0; kt < GNKT; kt++) {
        if (kt + 1 < GNKT) asm volatile("cp.async.wait_group 1;");
        else               asm volatile("cp.async.wait_group 0;");
        __syncthreads();

        const uint32_t as = as_base + buf * GBUF;
        const uint32_t bs = bs_base + buf * GBUF;

#pragma unroll
        for (int ks = 0; ks < 2; ks++) {
            uint32_t af[4][4];
#pragma unroll
            for (int mt = 0; mt < 4; mt++) {
                int row = wm * 64 + mt * 16 + (lane & 15);
                LDSM_X4(af[mt], as + row * GSTR + (ks * 2 + (lane >> 4)) * 16);
            }
            uint32_t bf[2][4];
#pragma unroll
            for (int bt = 0; bt < 2; bt++) {
                int nrow = wn * 32 + bt * 16 + (lane & 7) + ((lane >> 4) << 3);
                LDSM_X4(bf[bt], bs + nrow * GSTR + (ks * 2 + ((lane >> 3) & 1)) * 16);
            }
#pragma unroll
            for (int mt = 0; mt < 4; mt++)
#pragma unroll
                for (int nt = 0; nt < 4; nt++)
                    mma_f16(acc[mt][nt], af[mt],
                            bf[nt >> 1][(nt & 1) * 2], bf[nt >> 1][(nt & 1) * 2 + 1]);
        }
        __syncthreads();
        buf ^= 1;
        if (kt + 2 < GNKT) issue(kt + 2, buf ^ 1);
    }

    __half* stage = (__half*)smem;
#pragma unroll
    for (int mt = 0; mt < 4; mt++) {
        int rl = wm * 64 + mt * 16 + (lane >> 2);
#pragma unroll
        for (int nt = 0; nt < 4; nt++) {
            int cl = wn * 32 + nt * 8 + 2 * (lane & 3);
            int cg = blockCol + cl;
            float bx = bias[cg], by = bias[cg + 1];
            *(__half2*)(stage + rl * OSTR + cl) =
                __floats2half2_rn(acc[mt][nt][0] + bx, acc[mt][nt][1] + by);
            *(__half2*)(stage + (rl + 8) * OSTR + cl) =
                __floats2half2_rn(acc[mt][nt][2] + bx, acc[mt][nt][3] + by);
        }
    }
    __syncthreads();

    const int r_ = tid >> 4, ch = tid & 15;
#pragma unroll
    for (int it = 0; it < 8; it++) {
        int row = r_ + it * 16;
        int grow = blockRow + row;
        uint4 v = *(const uint4*)(stage + row * OSTR + ch * 8);
        if (grow < Mrows)
            *(uint4*)(C + (size_t)grow * Ncols + blockCol + ch * 8) = v;
    }
}

// ---------------- GRU elementwise (half2 gates) ----------------
__global__ void gru_kernel(const __half* __restrict__ gi, const __half* __restrict__ gh,
                           const float* __restrict__ h, float* __restrict__ out,
                           __half* __restrict__ hh) {
    int idx = blockIdx.x * blockDim.x + threadIdx.x;
    if (idx >= NNODES * (DDIM / 2)) return;
    int v = idx >> 7;
    int j = idx & 127;
    size_t b = (size_t)v * 384;
    const __half2* gi2 = (const __half2*)gi;
    const __half2* gh2 = (const __half2*)gh;
    float2 ir = __half22float2(gi2[b + j]);
    float2 hr = __half22float2(gh2[b + j]);
    float2 iz = __half22float2(gi2[b + 128 + j]);
    float2 hz = __half22float2(gh2[b + 128 + j]);
    float2 in_ = __half22float2(gi2[b + 256 + j]);
    float2 hn = __half22float2(gh2[b + 256 + j]);
    float2 hv = ((const float2*)h)[idx];

    float rx = 1.0f / (1.0f + expf(-(ir.x + hr.x)));
    float ry = 1.0f / (1.0f + expf(-(ir.y + hr.y)));
    float zx = 1.0f / (1.0f + expf(-(iz.x + hz.x)));
    float zy = 1.0f / (1.0f + expf(-(iz.y + hz.y)));
    float nx = tanhf(in_.x + rx * hn.x);
    float ny = tanhf(in_.y + ry * hn.y);
    float ox = (1.0f - zx) * nx + zx * hv.x;
    float oy = (1.0f - zy) * ny + zy * hv.y;
    ((float2*)out)[idx] = make_float2(ox, oy);
    if (hh != nullptr) ((__half2*)hh)[idx] = __floats2half2_rn(ox, oy);
}

// ---------------- launch ----------------
extern "C" void kernel_launch(void* const* d_in, const int* in_sizes, int n_in,
                              void* d_out, int out_size) {
    const float* node_states = (const float*)d_in[0];
    const float* W           = (const float*)d_in[1];
    const float* b           = (const float*)d_in[2];
    const float* w_ih        = (const float*)d_in[3];
    const float* w_hh        = (const float*)d_in[4];
    const float* b_ih        = (const float*)d_in[5];
    const float* b_hh        = (const float*)d_in[6];
    const int*   edges       = (const int*)d_in[7];
    float* out = (float*)d_out;

    float *h1;
    __half *proph, *msgsh, *gih, *ghh, *hh, *Wh, *wihh, *whhh;
    int *cnt, *rowptr, *cursor, *eidx;
    cudaGetSymbolAddress((void**)&proph,  g_proph);
    cudaGetSymbolAddress((void**)&msgsh,  g_msgsh);
    cudaGetSymbolAddress((void**)&gih,    g_gih);
    cudaGetSymbolAddress((void**)&ghh,    g_ghh);
    cudaGetSymbolAddress((void**)&h1,     g_h1);
    cudaGetSymbolAddress((void**)&hh,     g_hh);
    cudaGetSymbolAddress((void**)&Wh,     g_Wh);
    cudaGetSymbolAddress((void**)&wihh,   g_wihh);
    cudaGetSymbolAddress((void**)&whhh,   g_whhh);
    cudaGetSymbolAddress((void**)&cnt,    g_cnt);
    cudaGetSymbolAddress((void**)&rowptr, g_rowptr);
    cudaGetSymbolAddress((void**)&cursor, g_cursor);
    cudaGetSymbolAddress((void**)&eidx,   g_eidx);

    // Lazy creation: executes on the (non-captured) correctness call only.
    static cudaStream_t side = nullptr;
    static cudaEvent_t ev_fork = nullptr, ev_csr = nullptr;
    static cudaEvent_t evA[2] = {nullptr, nullptr}, evB[2] = {nullptr, nullptr};
    if (side == nullptr) {
        cudaStreamCreateWithFlags(&side, cudaStreamNonBlocking);
        cudaEventCreateWithFlags(&ev_fork, cudaEventDisableTiming);
        cudaEventCreateWithFlags(&ev_csr, cudaEventDisableTiming);
        for (int t = 0; t < 2; t++) {
            cudaEventCreateWithFlags(&evA[t], cudaEventDisableTiming);
            cudaEventCreateWithFlags(&evB[t], cudaEventDisableTiming);
        }
    }

    // ---- fork CSR build onto side stream ----
    cudaEventRecord(ev_fork, 0);
    cudaStreamWaitEvent(side, ev_fork, 0);
    cudaMemsetAsync(cnt, 0, NNODES * sizeof(int), side);
    count_kernel<<<(NEDGES + 255) / 256, 256, 0, side>>>(edges, cnt);
    scan_kernel<<<1, 1024, 0, side>>>(cnt, rowptr);
    cudaMemcpyAsync(cursor, rowptr, NNODES * sizeof(int), cudaMemcpyDeviceToDevice, side);
    fill_kernel<<<(NEDGES + 255) / 256, 256, 0, side>>>(edges, cursor, eidx);
    cudaEventRecord(ev_csr, side);

    // ---- main stream: operand conversion ----
    tohalf_kernel<<<(1536 * 256 / 4 + 255) / 256, 256>>>(W, Wh, 1536 * 256 / 4);
    tohalf_kernel<<<(768 * 256 / 4 + 255) / 256, 256>>>(w_ih, wihh, 768 * 256 / 4);
    tohalf_kernel<<<(768 * 256 / 4 + 255) / 256, 256>>>(w_hh, whhh, 768 * 256 / 4);
    tohalf_kernel<<<(NNODES * DDIM / 4 + 255) / 256, 256>>>(node_states, hh, NNODES * DDIM / 4);

    const int MT = (NNODES + GBM - 1) / GBM;
    const float* h = node_states;
    for (int t = 0; t < 2; t++) {
        // prop GEMM on main (needs hh, Wh)
        hgemm_abT<<<dim3(1536 / GBN, MT), 256>>>(hh, Wh, b, proph, NNODES, 1536);

        // fork: gh GEMM on side (needs hh + whhh; ordered after everything above on main)
        cudaEventRecord(evA[t], 0);
        cudaStreamWaitEvent(side, evA[t], 0);
        hgemm_abT<<<dim3(768 / GBN, MT), 256, 0, side>>>(hh, whhh, b_hh, ghh, NNODES, 768);
        cudaEventRecord(evB[t], side);

        // main: aggregate (needs CSR on first step) + gi GEMM
        if (t == 0) cudaStreamWaitEvent(0, ev_csr, 0);
        aggregate_kernel<<<(NNODES * 32 + 255) / 256, 256>>>(proph, rowptr, eidx, msgsh);
        hgemm_abT<<<dim3(768 / GBN, MT), 256>>>(msgsh, wihh, b_ih, gih, NNODES, 768);

        // join: gru needs ghh from side
        cudaStreamWaitEvent(0, evB[t], 0);
        float* hout = (t == 0) ? h1 : out;
        gru_kernel<<<(NNODES * DDIM / 2 + 255) / 256, 256>>>(gih, ghh, h, hout,
                                                             (t == 0) ? hh : nullptr);
        h = hout;
    }
}